// round 2
// baseline (speedup 1.0000x reference)
#include <cuda_runtime.h>
#include <math.h>

#define Bc 16
#define Lc 2048
#define Dc 192
#define Hc 4
#define Kc 12

// ---------------- scratch (no allocations allowed) ----------------
__device__ float g_xn [(size_t)Bc*Lc*Dc];       // xn1 then xn2 (reused)
__device__ float g_q  [(size_t)Bc*Hc*Lc*Kc];    // [B,H,L,K]
__device__ float g_k  [(size_t)Bc*Hc*Lc*Kc];
__device__ float g_v  [(size_t)Bc*Hc*Lc*Kc];
__device__ float g_ctx[(size_t)Bc*Lc*Hc*Kc];    // [B,L,H,K]
__device__ float g_y1 [(size_t)Bc*Lc*Dc];       // x + MHA
__device__ float g_h  [(size_t)Bc*Lc*Dc];       // relu(conv1), zero rows 0, L-1

__device__ __forceinline__ float ex2(float x) {
    float y; asm("ex2.approx.f32 %0, %1;" : "=f"(y) : "f"(x)); return y;
}

// ---------------- LayerNorm: one warp per row ----------------
template<int SRC>
__global__ void ln_kernel(const float* __restrict__ xin,
                          const float* __restrict__ gamma,
                          const float* __restrict__ beta)
{
    int gw   = (blockIdx.x * blockDim.x + threadIdx.x) >> 5;
    int lane = threadIdx.x & 31;
    if (gw >= Bc * Lc) return;
    const float* row = (SRC == 0 ? xin : g_y1) + (size_t)gw * Dc;
    float v[6];
    float s = 0.f;
#pragma unroll
    for (int i = 0; i < 6; i++) { v[i] = row[lane + 32*i]; s += v[i]; }
#pragma unroll
    for (int o = 16; o; o >>= 1) s += __shfl_xor_sync(0xffffffffu, s, o);
    float mean = s * (1.f/192.f);
    float vs = 0.f;
#pragma unroll
    for (int i = 0; i < 6; i++) { float d = v[i] - mean; vs += d*d; }
#pragma unroll
    for (int o = 16; o; o >>= 1) vs += __shfl_xor_sync(0xffffffffu, vs, o);
    float inv = rsqrtf(vs * (1.f/192.f) + 1e-3f);
#pragma unroll
    for (int i = 0; i < 6; i++) {
        int c = lane + 32*i;
        g_xn[(size_t)gw * Dc + c] = (v[i] - mean) * inv * gamma[c] + beta[c];
    }
}

// ---------------- QKV projection: block = 16 rows x 144 outputs ----------------
__global__ void qkv_kernel(const float* __restrict__ wq, const float* __restrict__ bq,
                           const float* __restrict__ wk, const float* __restrict__ bk,
                           const float* __restrict__ wv, const float* __restrict__ bv)
{
    __shared__ float sx[16 * Dc];
    int rowbase = blockIdx.x * 16;
    int tid = threadIdx.x;                  // 144 threads
    {
        const float4* src4 = (const float4*)(g_xn + (size_t)rowbase * Dc);
        float4* sx4 = (float4*)sx;
        for (int idx = tid; idx < 16 * Dc / 4; idx += 144) sx4[idx] = src4[idx];
    }
    __syncthreads();

    int s   = tid / 48;                     // 0=q 1=k 2=v
    int j48 = tid % 48;
    const float* W  = (s == 0) ? wq : (s == 1) ? wk : wv;
    const float* Bp = (s == 0) ? bq : (s == 1) ? bk : bv;
    float acc[16];
#pragma unroll
    for (int r = 0; r < 16; r++) acc[r] = 0.f;

    const float4* sx4 = (const float4*)sx;
#pragma unroll 2
    for (int d4 = 0; d4 < 48; d4++) {
        float w0 = W[(4*d4+0)*48 + j48];
        float w1 = W[(4*d4+1)*48 + j48];
        float w2 = W[(4*d4+2)*48 + j48];
        float w3 = W[(4*d4+3)*48 + j48];
#pragma unroll
        for (int r = 0; r < 16; r++) {
            float4 xv = sx4[r*48 + d4];
            acc[r] = fmaf(xv.x, w0, fmaf(xv.y, w1, fmaf(xv.z, w2, fmaf(xv.w, w3, acc[r]))));
        }
    }
    int h = j48 / Kc, kk = j48 % Kc;
    float bias = Bp[j48];
    float* O = (s == 0) ? g_q : (s == 1) ? g_k : g_v;
#pragma unroll
    for (int r = 0; r < 16; r++) {
        int row = rowbase + r;
        int bb = row / Lc, l = row % Lc;
        O[(((size_t)bb * Hc + h) * Lc + l) * Kc + kk] = acc[r] + bias;
    }
}

// ---------------- causal attention (flash-style, no-max softmax) ----------------
// block: 128 threads, 256 queries (2 per thread). K/V tiles of 128 keys in SMEM.
// q pre-scaled by log2(e)/sqrt(K) so p = 2^(q.k) == exp(score/sqrt(K)).
template<int MODE>
__device__ __forceinline__ void attn_tile(const float4* __restrict__ sk,
                                          const float4* __restrict__ sv,
                                          int mbase, int l1, int l2,
                                          const float* q1, const float* q2,
                                          float* o1, float* o2,
                                          float& d1, float& d2)
{
#pragma unroll 4
    for (int mm = 0; mm < 128; mm++) {
        float4 ka = sk[3*mm], kb = sk[3*mm+1], kc = sk[3*mm+2];
        int m = mbase + mm;
        float p1 = 0.f;
        if (MODE < 2) {
            float s1 = q1[0]*ka.x + q1[1]*ka.y + q1[2]*ka.z + q1[3]*ka.w
                     + q1[4]*kb.x + q1[5]*kb.y + q1[6]*kb.z + q1[7]*kb.w
                     + q1[8]*kc.x + q1[9]*kc.y + q1[10]*kc.z + q1[11]*kc.w;
            p1 = ex2(s1);
            if (MODE == 1 && m > l1) p1 = 0.f;
        }
        float s2 = q2[0]*ka.x + q2[1]*ka.y + q2[2]*ka.z + q2[3]*ka.w
                 + q2[4]*kb.x + q2[5]*kb.y + q2[6]*kb.z + q2[7]*kb.w
                 + q2[8]*kc.x + q2[9]*kc.y + q2[10]*kc.z + q2[11]*kc.w;
        float p2 = ex2(s2);
        if (MODE == 2 && m > l2) p2 = 0.f;
        d1 += p1; d2 += p2;
        float4 va = sv[3*mm], vb = sv[3*mm+1], vc = sv[3*mm+2];
        if (MODE < 2) {
            o1[0] += p1*va.x; o1[1] += p1*va.y; o1[2]  += p1*va.z; o1[3]  += p1*va.w;
            o1[4] += p1*vb.x; o1[5] += p1*vb.y; o1[6]  += p1*vb.z; o1[7]  += p1*vb.w;
            o1[8] += p1*vc.x; o1[9] += p1*vc.y; o1[10] += p1*vc.z; o1[11] += p1*vc.w;
        }
        o2[0] += p2*va.x; o2[1] += p2*va.y; o2[2]  += p2*va.z; o2[3]  += p2*va.w;
        o2[4] += p2*vb.x; o2[5] += p2*vb.y; o2[6]  += p2*vb.z; o2[7]  += p2*vb.w;
        o2[8] += p2*vc.x; o2[9] += p2*vc.y; o2[10] += p2*vc.z; o2[11] += p2*vc.w;
    }
}

__global__ void attn_kernel()
{
    __shared__ float4 sk[128 * 3];
    __shared__ float4 sv[128 * 3];
    int qt = gridDim.x - 1 - blockIdx.x;    // heavy tiles first
    int h = blockIdx.y, bb = blockIdx.z;
    int t = threadIdx.x;
    int l1 = qt * 256 + t;
    int l2 = l1 + 128;

    size_t head = ((size_t)bb * Hc + h) * Lc * Kc;
    const float4* qb = (const float4*)(g_q + head);
    const float*  kb = g_k + head;
    const float*  vb = g_v + head;

    const float scale = 0.4164682333693345f;   // log2(e)/sqrt(12)
    float q1[12], q2[12];
    {
        float4 a = qb[3*l1], b = qb[3*l1+1], c = qb[3*l1+2];
        q1[0]=a.x*scale; q1[1]=a.y*scale; q1[2]=a.z*scale; q1[3]=a.w*scale;
        q1[4]=b.x*scale; q1[5]=b.y*scale; q1[6]=b.z*scale; q1[7]=b.w*scale;
        q1[8]=c.x*scale; q1[9]=c.y*scale; q1[10]=c.z*scale; q1[11]=c.w*scale;
        a = qb[3*l2]; b = qb[3*l2+1]; c = qb[3*l2+2];
        q2[0]=a.x*scale; q2[1]=a.y*scale; q2[2]=a.z*scale; q2[3]=a.w*scale;
        q2[4]=b.x*scale; q2[5]=b.y*scale; q2[6]=b.z*scale; q2[7]=b.w*scale;
        q2[8]=c.x*scale; q2[9]=c.y*scale; q2[10]=c.z*scale; q2[11]=c.w*scale;
    }
    float o1[12], o2[12];
#pragma unroll
    for (int i = 0; i < 12; i++) { o1[i] = 0.f; o2[i] = 0.f; }
    float d1 = 0.f, d2 = 0.f;

    int full = 2 * qt;   // tiles with no masking at all
    for (int kt = 0; kt <= full + 1; kt++) {
        __syncthreads();
        const float4* ks = (const float4*)(kb + (size_t)kt * 128 * Kc);
        const float4* vs = (const float4*)(vb + (size_t)kt * 128 * Kc);
        for (int i = t; i < 128 * 3; i += 128) { sk[i] = ks[i]; sv[i] = vs[i]; }
        __syncthreads();
        int mbase = kt * 128;
        if      (kt <  full) attn_tile<0>(sk, sv, mbase, l1, l2, q1, q2, o1, o2, d1, d2);
        else if (kt == full) attn_tile<1>(sk, sv, mbase, l1, l2, q1, q2, o1, o2, d1, d2);
        else                 attn_tile<2>(sk, sv, mbase, l1, l2, q1, q2, o1, o2, d1, d2);
    }

    float i1 = 1.f / d1, i2 = 1.f / d2;
    float4* out1 = (float4*)(g_ctx + (((size_t)bb * Lc + l1) * Hc + h) * Kc);
    float4* out2 = (float4*)(g_ctx + (((size_t)bb * Lc + l2) * Hc + h) * Kc);
    out1[0] = make_float4(o1[0]*i1, o1[1]*i1, o1[2]*i1,  o1[3]*i1);
    out1[1] = make_float4(o1[4]*i1, o1[5]*i1, o1[6]*i1,  o1[7]*i1);
    out1[2] = make_float4(o1[8]*i1, o1[9]*i1, o1[10]*i1, o1[11]*i1);
    out2[0] = make_float4(o2[0]*i2, o2[1]*i2, o2[2]*i2,  o2[3]*i2);
    out2[1] = make_float4(o2[4]*i2, o2[5]*i2, o2[6]*i2,  o2[7]*i2);
    out2[2] = make_float4(o2[8]*i2, o2[9]*i2, o2[10]*i2, o2[11]*i2);
}

// ---------------- output projection + residual ----------------
__global__ void proj_kernel(const float* __restrict__ x,
                            const float* __restrict__ wo,
                            const float* __restrict__ bo)
{
    __shared__ float sc[16 * 48];
    int rowbase = blockIdx.x * 16;
    int j = threadIdx.x;                    // 192 threads = output column
    {
        const float4* src4 = (const float4*)(g_ctx + (size_t)rowbase * 48);
        float4* sc4 = (float4*)sc;
        for (int idx = j; idx < 16 * 48 / 4; idx += 192) sc4[idx] = src4[idx];
    }
    __syncthreads();
    float acc[16];
#pragma unroll
    for (int r = 0; r < 16; r++) acc[r] = 0.f;
    const float4* sc4 = (const float4*)sc;
#pragma unroll
    for (int i4 = 0; i4 < 12; i4++) {
        float w0 = wo[(4*i4+0)*Dc + j];
        float w1 = wo[(4*i4+1)*Dc + j];
        float w2 = wo[(4*i4+2)*Dc + j];
        float w3 = wo[(4*i4+3)*Dc + j];
#pragma unroll
        for (int r = 0; r < 16; r++) {
            float4 cv = sc4[r*12 + i4];
            acc[r] = fmaf(cv.x, w0, fmaf(cv.y, w1, fmaf(cv.z, w2, fmaf(cv.w, w3, acc[r]))));
        }
    }
    float bias = bo[j];
#pragma unroll
    for (int r = 0; r < 16; r++) {
        size_t o = (size_t)(rowbase + r) * Dc + j;
        g_y1[o] = acc[r] + bias + x[o];
    }
}

// ---------------- conv1d (kernel 3, VALID) as GEMM ----------------
// block: 64 rows x 192 cols. 384 threads = 4 row-groups x 96 col-threads.
// Each thread: 16 rows x 2 cols. 64-row input tile in smem (48KB); the +-1
// halo rows of boundary groups come straight from gmem (L2/L1-resident).
// MODE 0: src=g_xn, dst=g_h, relu, zero rows 0 / L-1.
// MODE 1: src=g_h, dst=out (final), add g_y1 residual, zero conv part rows 0 / L-1.
template<int MODE>
__global__ __launch_bounds__(384, 2)
void conv_kernel(const float* __restrict__ W,
                 const float* __restrict__ bias,
                 float* __restrict__ out)
{
    __shared__ float sx[64 * Dc];           // 49152 B
    int l0 = blockIdx.x * 64;
    int bb = blockIdx.y;
    int tid = threadIdx.x;                  // 384
    int g = tid / 96, t96 = tid % 96;
    int r0 = g * 16;
    int j = t96 * 2;
    const float* srcb = ((MODE == 0) ? g_xn : g_h) + (size_t)bb * Lc * Dc;

    {
        const float4* s4 = (const float4*)(srcb + (size_t)l0 * Dc);
        float4* sx4 = (float4*)sx;
        for (int idx = tid; idx < 64 * Dc / 4; idx += 384) sx4[idx] = s4[idx];
    }
    __syncthreads();

    int lm = l0 + r0 - 1;  if (lm < 0) lm = 0;             // g==0 halo row
    int lp = l0 + r0 + 16; if (lp > Lc - 1) lp = Lc - 1;   // g==3 halo row
    const float* rowm = srcb + (size_t)lm * Dc;
    const float* rowp = srcb + (size_t)lp * Dc;
    int rm_s = (g == 0) ? 0 : (r0 - 1);     // safe smem fallback indices
    int rp_s = (g == 3) ? 0 : (r0 + 16);

    float a0[16], a1[16];
#pragma unroll
    for (int r = 0; r < 16; r++) { a0[r] = 0.f; a1[r] = 0.f; }

    for (int c = 0; c < Dc; c++) {
        float in[18];
        in[0]  = (g == 0) ? __ldg(rowm + c) : sx[rm_s * Dc + c];
#pragma unroll
        for (int rr = 1; rr < 17; rr++) in[rr] = sx[(r0 - 1 + rr) * Dc + c];
        in[17] = (g == 3) ? __ldg(rowp + c) : sx[rp_s * Dc + c];
#pragma unroll
        for (int tt = 0; tt < 3; tt++) {
            float2 w = *(const float2*)(W + ((size_t)(tt * Dc + c)) * Dc + j);
#pragma unroll
            for (int r = 0; r < 16; r++) {
                a0[r] = fmaf(in[r + tt], w.x, a0[r]);
                a1[r] = fmaf(in[r + tt], w.y, a1[r]);
            }
        }
    }

    float b0 = bias[j], b1 = bias[j + 1];
    float* dst = (MODE == 0) ? g_h : out;
#pragma unroll
    for (int r = 0; r < 16; r++) {
        int l = l0 + r0 + r;
        bool interior = (l >= 1) && (l <= Lc - 2);
        size_t o = ((size_t)bb * Lc + l) * Dc + j;
        float v0 = a0[r] + b0, v1 = a1[r] + b1;
        float2 res;
        if (MODE == 0) {
            res.x = interior ? fmaxf(v0, 0.f) : 0.f;
            res.y = interior ? fmaxf(v1, 0.f) : 0.f;
        } else {
            float2 y = *(const float2*)(g_y1 + o);
            res.x = y.x + (interior ? v0 : 0.f);
            res.y = y.y + (interior ? v1 : 0.f);
        }
        *(float2*)(dst + o) = res;
    }
}

// ---------------- launcher ----------------
extern "C" void kernel_launch(void* const* d_in, const int* in_sizes, int n_in,
                              void* d_out, int out_size)
{
    const float* x     = (const float*)d_in[0];
    const float* ln1_g = (const float*)d_in[1];
    const float* ln1_b = (const float*)d_in[2];
    const float* wq    = (const float*)d_in[3];
    const float* bq    = (const float*)d_in[4];
    const float* wk    = (const float*)d_in[5];
    const float* bk    = (const float*)d_in[6];
    const float* wv    = (const float*)d_in[7];
    const float* bv    = (const float*)d_in[8];
    const float* wo    = (const float*)d_in[9];
    const float* bo    = (const float*)d_in[10];
    const float* ln2_g = (const float*)d_in[11];
    const float* ln2_b = (const float*)d_in[12];
    const float* c1_w  = (const float*)d_in[13];
    const float* c1_b  = (const float*)d_in[14];
    const float* c2_w  = (const float*)d_in[15];
    const float* c2_b  = (const float*)d_in[16];
    float* outp = (float*)d_out;

    ln_kernel<0><<<(Bc*Lc)/8, 256>>>(x, ln1_g, ln1_b);
    qkv_kernel<<<(Bc*Lc)/16, 144>>>(wq, bq, wk, bk, wv, bv);
    attn_kernel<<<dim3(Lc/256, Hc, Bc), 128>>>();
    proj_kernel<<<(Bc*Lc)/16, 192>>>(x, wo, bo);
    ln_kernel<1><<<(Bc*Lc)/8, 256>>>(x, ln2_g, ln2_b);
    conv_kernel<0><<<dim3(Lc/64, Bc), 384>>>(c1_w, c1_b, outp);
    conv_kernel<1><<<dim3(Lc/64, Bc), 384>>>(c2_w, c2_b, outp);
}

// round 3
// speedup vs baseline: 1.4337x; 1.4337x over previous
#include <cuda_runtime.h>
#include <math.h>
#include <stdint.h>

#define Bc 16
#define Lc 2048
#define Dc 192
#define Hc 4
#define Kc 12

// ---------------- scratch (no allocations allowed) ----------------
__device__ float g_xn [(size_t)Bc*Lc*Dc];       // xn1 then xn2 (reused)
__device__ float g_q  [(size_t)Bc*Hc*Lc*Kc];    // [B,H,L,K]
__device__ float g_k  [(size_t)Bc*Hc*Lc*Kc];
__device__ float g_v  [(size_t)Bc*Hc*Lc*Kc];
__device__ float g_ctx[(size_t)Bc*Lc*Hc*Kc];    // [B,L,H,K]
__device__ float g_y1 [(size_t)Bc*Lc*Dc];       // x + MHA
__device__ float g_h  [(size_t)Bc*Lc*Dc];       // relu(conv1), zero rows 0, L-1

__device__ __forceinline__ float ex2(float x) {
    float y; asm("ex2.approx.f32 %0, %1;" : "=f"(y) : "f"(x)); return y;
}
__device__ __forceinline__ float to_tf32(float x) {
    uint32_t u; asm("cvt.rna.tf32.f32 %0, %1;" : "=r"(u) : "f"(x));
    return __uint_as_float(u);
}

// ---------------- LayerNorm: one warp per row ----------------
template<int SRC>
__global__ void ln_kernel(const float* __restrict__ xin,
                          const float* __restrict__ gamma,
                          const float* __restrict__ beta)
{
    int gw   = (blockIdx.x * blockDim.x + threadIdx.x) >> 5;
    int lane = threadIdx.x & 31;
    if (gw >= Bc * Lc) return;
    const float* row = (SRC == 0 ? xin : g_y1) + (size_t)gw * Dc;
    float v[6];
    float s = 0.f;
#pragma unroll
    for (int i = 0; i < 6; i++) { v[i] = row[lane + 32*i]; s += v[i]; }
#pragma unroll
    for (int o = 16; o; o >>= 1) s += __shfl_xor_sync(0xffffffffu, s, o);
    float mean = s * (1.f/192.f);
    float vs = 0.f;
#pragma unroll
    for (int i = 0; i < 6; i++) { float d = v[i] - mean; vs += d*d; }
#pragma unroll
    for (int o = 16; o; o >>= 1) vs += __shfl_xor_sync(0xffffffffu, vs, o);
    float inv = rsqrtf(vs * (1.f/192.f) + 1e-3f);
#pragma unroll
    for (int i = 0; i < 6; i++) {
        int c = lane + 32*i;
        g_xn[(size_t)gw * Dc + c] = (v[i] - mean) * inv * gamma[c] + beta[c];
    }
}

// ---------------- QKV projection: block = 16 rows x 144 outputs ----------------
__global__ void qkv_kernel(const float* __restrict__ wq, const float* __restrict__ bq,
                           const float* __restrict__ wk, const float* __restrict__ bk,
                           const float* __restrict__ wv, const float* __restrict__ bv)
{
    __shared__ float sx[16 * Dc];
    int rowbase = blockIdx.x * 16;
    int tid = threadIdx.x;                  // 144 threads
    {
        const float4* src4 = (const float4*)(g_xn + (size_t)rowbase * Dc);
        float4* sx4 = (float4*)sx;
        for (int idx = tid; idx < 16 * Dc / 4; idx += 144) sx4[idx] = src4[idx];
    }
    __syncthreads();

    int s   = tid / 48;                     // 0=q 1=k 2=v
    int j48 = tid % 48;
    const float* W  = (s == 0) ? wq : (s == 1) ? wk : wv;
    const float* Bp = (s == 0) ? bq : (s == 1) ? bk : bv;
    float acc[16];
#pragma unroll
    for (int r = 0; r < 16; r++) acc[r] = 0.f;

    const float4* sx4 = (const float4*)sx;
#pragma unroll 2
    for (int d4 = 0; d4 < 48; d4++) {
        float w0 = W[(4*d4+0)*48 + j48];
        float w1 = W[(4*d4+1)*48 + j48];
        float w2 = W[(4*d4+2)*48 + j48];
        float w3 = W[(4*d4+3)*48 + j48];
#pragma unroll
        for (int r = 0; r < 16; r++) {
            float4 xv = sx4[r*48 + d4];
            acc[r] = fmaf(xv.x, w0, fmaf(xv.y, w1, fmaf(xv.z, w2, fmaf(xv.w, w3, acc[r]))));
        }
    }
    int h = j48 / Kc, kk = j48 % Kc;
    float bias = Bp[j48];
    float* O = (s == 0) ? g_q : (s == 1) ? g_k : g_v;
#pragma unroll
    for (int r = 0; r < 16; r++) {
        int row = rowbase + r;
        int bb = row / Lc, l = row % Lc;
        O[(((size_t)bb * Hc + h) * Lc + l) * Kc + kk] = acc[r] + bias;
    }
}

// ---------------- causal attention (flash-style, no-max softmax) ----------------
template<int MODE>
__device__ __forceinline__ void attn_tile(const float4* __restrict__ sk,
                                          const float4* __restrict__ sv,
                                          int mbase, int l1, int l2,
                                          const float* q1, const float* q2,
                                          float* o1, float* o2,
                                          float& d1, float& d2)
{
#pragma unroll 4
    for (int mm = 0; mm < 128; mm++) {
        float4 ka = sk[3*mm], kb = sk[3*mm+1], kc = sk[3*mm+2];
        int m = mbase + mm;
        float p1 = 0.f;
        if (MODE < 2) {
            float s1 = q1[0]*ka.x + q1[1]*ka.y + q1[2]*ka.z + q1[3]*ka.w
                     + q1[4]*kb.x + q1[5]*kb.y + q1[6]*kb.z + q1[7]*kb.w
                     + q1[8]*kc.x + q1[9]*kc.y + q1[10]*kc.z + q1[11]*kc.w;
            p1 = ex2(s1);
            if (MODE == 1 && m > l1) p1 = 0.f;
        }
        float s2 = q2[0]*ka.x + q2[1]*ka.y + q2[2]*ka.z + q2[3]*ka.w
                 + q2[4]*kb.x + q2[5]*kb.y + q2[6]*kb.z + q2[7]*kb.w
                 + q2[8]*kc.x + q2[9]*kc.y + q2[10]*kc.z + q2[11]*kc.w;
        float p2 = ex2(s2);
        if (MODE == 2 && m > l2) p2 = 0.f;
        d1 += p1; d2 += p2;
        float4 va = sv[3*mm], vb = sv[3*mm+1], vc = sv[3*mm+2];
        if (MODE < 2) {
            o1[0] += p1*va.x; o1[1] += p1*va.y; o1[2]  += p1*va.z; o1[3]  += p1*va.w;
            o1[4] += p1*vb.x; o1[5] += p1*vb.y; o1[6]  += p1*vb.z; o1[7]  += p1*vb.w;
            o1[8] += p1*vc.x; o1[9] += p1*vc.y; o1[10] += p1*vc.z; o1[11] += p1*vc.w;
        }
        o2[0] += p2*va.x; o2[1] += p2*va.y; o2[2]  += p2*va.z; o2[3]  += p2*va.w;
        o2[4] += p2*vb.x; o2[5] += p2*vb.y; o2[6]  += p2*vb.z; o2[7]  += p2*vb.w;
        o2[8] += p2*vc.x; o2[9] += p2*vc.y; o2[10] += p2*vc.z; o2[11] += p2*vc.w;
    }
}

__global__ void attn_kernel()
{
    __shared__ float4 sk[128 * 3];
    __shared__ float4 sv[128 * 3];
    int qt = gridDim.x - 1 - blockIdx.x;    // heavy tiles first
    int h = blockIdx.y, bb = blockIdx.z;
    int t = threadIdx.x;
    int l1 = qt * 256 + t;
    int l2 = l1 + 128;

    size_t head = ((size_t)bb * Hc + h) * Lc * Kc;
    const float4* qb = (const float4*)(g_q + head);
    const float*  kb = g_k + head;
    const float*  vb = g_v + head;

    const float scale = 0.4164682333693345f;   // log2(e)/sqrt(12)
    float q1[12], q2[12];
    {
        float4 a = qb[3*l1], b = qb[3*l1+1], c = qb[3*l1+2];
        q1[0]=a.x*scale; q1[1]=a.y*scale; q1[2]=a.z*scale; q1[3]=a.w*scale;
        q1[4]=b.x*scale; q1[5]=b.y*scale; q1[6]=b.z*scale; q1[7]=b.w*scale;
        q1[8]=c.x*scale; q1[9]=c.y*scale; q1[10]=c.z*scale; q1[11]=c.w*scale;
        a = qb[3*l2]; b = qb[3*l2+1]; c = qb[3*l2+2];
        q2[0]=a.x*scale; q2[1]=a.y*scale; q2[2]=a.z*scale; q2[3]=a.w*scale;
        q2[4]=b.x*scale; q2[5]=b.y*scale; q2[6]=b.z*scale; q2[7]=b.w*scale;
        q2[8]=c.x*scale; q2[9]=c.y*scale; q2[10]=c.z*scale; q2[11]=c.w*scale;
    }
    float o1[12], o2[12];
#pragma unroll
    for (int i = 0; i < 12; i++) { o1[i] = 0.f; o2[i] = 0.f; }
    float d1 = 0.f, d2 = 0.f;

    int full = 2 * qt;   // tiles with no masking at all
    for (int kt = 0; kt <= full + 1; kt++) {
        __syncthreads();
        const float4* ks = (const float4*)(kb + (size_t)kt * 128 * Kc);
        const float4* vs = (const float4*)(vb + (size_t)kt * 128 * Kc);
        for (int i = t; i < 128 * 3; i += 128) { sk[i] = ks[i]; sv[i] = vs[i]; }
        __syncthreads();
        int mbase = kt * 128;
        if      (kt <  full) attn_tile<0>(sk, sv, mbase, l1, l2, q1, q2, o1, o2, d1, d2);
        else if (kt == full) attn_tile<1>(sk, sv, mbase, l1, l2, q1, q2, o1, o2, d1, d2);
        else                 attn_tile<2>(sk, sv, mbase, l1, l2, q1, q2, o1, o2, d1, d2);
    }

    float i1 = 1.f / d1, i2 = 1.f / d2;
    float4* out1 = (float4*)(g_ctx + (((size_t)bb * Lc + l1) * Hc + h) * Kc);
    float4* out2 = (float4*)(g_ctx + (((size_t)bb * Lc + l2) * Hc + h) * Kc);
    out1[0] = make_float4(o1[0]*i1, o1[1]*i1, o1[2]*i1,  o1[3]*i1);
    out1[1] = make_float4(o1[4]*i1, o1[5]*i1, o1[6]*i1,  o1[7]*i1);
    out1[2] = make_float4(o1[8]*i1, o1[9]*i1, o1[10]*i1, o1[11]*i1);
    out2[0] = make_float4(o2[0]*i2, o2[1]*i2, o2[2]*i2,  o2[3]*i2);
    out2[1] = make_float4(o2[4]*i2, o2[5]*i2, o2[6]*i2,  o2[7]*i2);
    out2[2] = make_float4(o2[8]*i2, o2[9]*i2, o2[10]*i2, o2[11]*i2);
}

// ---------------- output projection + residual ----------------
__global__ void proj_kernel(const float* __restrict__ x,
                            const float* __restrict__ wo,
                            const float* __restrict__ bo)
{
    __shared__ float sc[16 * 48];
    int rowbase = blockIdx.x * 16;
    int j = threadIdx.x;                    // 192 threads = output column
    {
        const float4* src4 = (const float4*)(g_ctx + (size_t)rowbase * 48);
        float4* sc4 = (float4*)sc;
        for (int idx = j; idx < 16 * 48 / 4; idx += 192) sc4[idx] = src4[idx];
    }
    __syncthreads();
    float acc[16];
#pragma unroll
    for (int r = 0; r < 16; r++) acc[r] = 0.f;
    const float4* sc4 = (const float4*)sc;
#pragma unroll
    for (int i4 = 0; i4 < 12; i4++) {
        float w0 = wo[(4*i4+0)*Dc + j];
        float w1 = wo[(4*i4+1)*Dc + j];
        float w2 = wo[(4*i4+2)*Dc + j];
        float w3 = wo[(4*i4+3)*Dc + j];
#pragma unroll
        for (int r = 0; r < 16; r++) {
            float4 cv = sc4[r*12 + i4];
            acc[r] = fmaf(cv.x, w0, fmaf(cv.y, w1, fmaf(cv.z, w2, fmaf(cv.w, w3, acc[r]))));
        }
    }
    float bias = bo[j];
#pragma unroll
    for (int r = 0; r < 16; r++) {
        size_t o = (size_t)(rowbase + r) * Dc + j;
        g_y1[o] = acc[r] + bias + x[o];
    }
}

// ---------------- conv1d as tf32 tensor-core GEMM ----------------
// out[l, n] = sum_{t,c} in[l-1+t, c] * W[t, c, n]   (M=64/block, N=192, K=576)
// 256 threads = 8 warps; warp -> 2 m-tiles (m16) x 6 n-tiles (n8), mma.m16n8k8.
// smem: input tile [66][196] (pad: conflict-free A loads), W double-buffered
// K-chunks [2][32][200] (pad: conflict-free B loads).  ~101 KB dynamic, 2 blk/SM.
#define SA_STRIDE 196
#define SB_STRIDE 200
#define SA_FLOATS (66 * SA_STRIDE)
#define SB_FLOATS (32 * SB_STRIDE)
#define CONV_SMEM_BYTES ((SA_FLOATS + 2 * SB_FLOATS) * 4)

__device__ __forceinline__ void mma_tf32(float* c, const uint32_t* a,
                                         uint32_t b0, uint32_t b1)
{
    asm volatile(
        "mma.sync.aligned.m16n8k8.row.col.f32.tf32.tf32.f32 "
        "{%0,%1,%2,%3}, {%4,%5,%6,%7}, {%8,%9}, {%0,%1,%2,%3};"
        : "+f"(c[0]), "+f"(c[1]), "+f"(c[2]), "+f"(c[3])
        : "r"(a[0]), "r"(a[1]), "r"(a[2]), "r"(a[3]), "r"(b0), "r"(b1));
}

template<int MODE>
__global__ __launch_bounds__(256, 2)
void conv_mma_kernel(const float* __restrict__ W,
                     const float* __restrict__ bias,
                     float* __restrict__ out)
{
    extern __shared__ float smem[];
    float* sA = smem;                    // [66][196]
    float* sB = smem + SA_FLOATS;        // [2][32][200]

    const int tid  = threadIdx.x;
    const int w    = tid >> 5;
    const int lane = tid & 31;
    const int tig  = lane & 3;           // threadID_in_group
    const int grp  = lane >> 2;          // groupID
    const int l0   = blockIdx.x * 64;
    const int bb   = blockIdx.y;
    const float* srcb = ((MODE == 0) ? g_xn : g_h) + (size_t)bb * Lc * Dc;

    // input rows l0-1 .. l0+64 (clamped) -> tf32 in smem
    for (int idx = tid; idx < 66 * 48; idx += 256) {
        int r = idx / 48, c4 = (idx % 48) * 4;
        int l = l0 - 1 + r; l = l < 0 ? 0 : (l > Lc - 1 ? Lc - 1 : l);
        float4 v = *(const float4*)(srcb + (size_t)l * Dc + c4);
        float* d = sA + r * SA_STRIDE + c4;
        d[0] = to_tf32(v.x); d[1] = to_tf32(v.y);
        d[2] = to_tf32(v.z); d[3] = to_tf32(v.w);
    }

    const int mbase = (w & 1) * 32;
    const int nbase = (w >> 1) * 48;
    float c[2][6][4];
#pragma unroll
    for (int i = 0; i < 2; i++)
#pragma unroll
        for (int j = 0; j < 6; j++)
#pragma unroll
            for (int q = 0; q < 4; q++) c[i][j][q] = 0.f;

    // load W chunk kc into buffer bf
    auto loadW = [&](int kc, int bf) {
        float* dstb = sB + bf * SB_FLOATS;
#pragma unroll
        for (int it = 0; it < 6; it++) {
            int idx = tid + it * 256;            // 32*48 = 1536 float4
            int k = idx / 48, c4 = (idx % 48) * 4;
            float4 v = *(const float4*)(W + ((size_t)(kc * 32 + k)) * Dc + c4);
            float* d = dstb + k * SB_STRIDE + c4;
            d[0] = to_tf32(v.x); d[1] = to_tf32(v.y);
            d[2] = to_tf32(v.z); d[3] = to_tf32(v.w);
        }
    };

    loadW(0, 0);
    __syncthreads();

    int buf = 0;
    for (int kc = 0; kc < 18; kc++) {
        if (kc < 17) loadW(kc + 1, buf ^ 1);
        const int t  = kc / 6;                   // conv tap
        const int cc = (kc % 6) * 32;            // channel base of this chunk
        const float* bBuf = sB + buf * SB_FLOATS;
#pragma unroll
        for (int ks = 0; ks < 4; ks++) {
            const int c0 = cc + ks * 8;
            uint32_t a[2][4];
#pragma unroll
            for (int mt = 0; mt < 2; mt++) {
                const float* ap = sA + (mbase + mt * 16 + grp + t) * SA_STRIDE + c0 + tig;
                a[mt][0] = __float_as_uint(ap[0]);
                a[mt][1] = __float_as_uint(ap[8 * SA_STRIDE]);
                a[mt][2] = __float_as_uint(ap[4]);
                a[mt][3] = __float_as_uint(ap[8 * SA_STRIDE + 4]);
            }
            const float* bp = bBuf + (ks * 8 + tig) * SB_STRIDE + nbase + grp;
#pragma unroll
            for (int nt = 0; nt < 6; nt++) {
                uint32_t b0 = __float_as_uint(bp[nt * 8]);
                uint32_t b1 = __float_as_uint(bp[nt * 8 + 4 * SB_STRIDE]);
                mma_tf32(c[0][nt], a[0], b0, b1);
                mma_tf32(c[1][nt], a[1], b0, b1);
            }
        }
        __syncthreads();
        buf ^= 1;
    }

    // epilogue
    float* dst = (MODE == 0) ? g_h : out;
#pragma unroll
    for (int mt = 0; mt < 2; mt++) {
#pragma unroll
        for (int rs = 0; rs < 2; rs++) {
            int l = l0 + mbase + mt * 16 + grp + rs * 8;
            bool interior = (l >= 1) && (l <= Lc - 2);
            size_t rowoff = ((size_t)bb * Lc + l) * Dc;
#pragma unroll
            for (int nt = 0; nt < 6; nt++) {
                int n = nbase + nt * 8 + tig * 2;
                float v0 = c[mt][nt][rs * 2 + 0] + bias[n];
                float v1 = c[mt][nt][rs * 2 + 1] + bias[n + 1];
                float2 res;
                if (MODE == 0) {
                    res.x = interior ? fmaxf(v0, 0.f) : 0.f;
                    res.y = interior ? fmaxf(v1, 0.f) : 0.f;
                } else {
                    float2 y = *(const float2*)(g_y1 + rowoff + n);
                    res.x = y.x + (interior ? v0 : 0.f);
                    res.y = y.y + (interior ? v1 : 0.f);
                }
                *(float2*)(dst + rowoff + n) = res;
            }
        }
    }
}

// ---------------- launcher ----------------
extern "C" void kernel_launch(void* const* d_in, const int* in_sizes, int n_in,
                              void* d_out, int out_size)
{
    const float* x     = (const float*)d_in[0];
    const float* ln1_g = (const float*)d_in[1];
    const float* ln1_b = (const float*)d_in[2];
    const float* wq    = (const float*)d_in[3];
    const float* bq    = (const float*)d_in[4];
    const float* wk    = (const float*)d_in[5];
    const float* bk    = (const float*)d_in[6];
    const float* wv    = (const float*)d_in[7];
    const float* bv    = (const float*)d_in[8];
    const float* wo    = (const float*)d_in[9];
    const float* bo    = (const float*)d_in[10];
    const float* ln2_g = (const float*)d_in[11];
    const float* ln2_b = (const float*)d_in[12];
    const float* c1_w  = (const float*)d_in[13];
    const float* c1_b  = (const float*)d_in[14];
    const float* c2_w  = (const float*)d_in[15];
    const float* c2_b  = (const float*)d_in[16];
    float* outp = (float*)d_out;

    cudaFuncSetAttribute(conv_mma_kernel<0>,
                         cudaFuncAttributeMaxDynamicSharedMemorySize, CONV_SMEM_BYTES);
    cudaFuncSetAttribute(conv_mma_kernel<1>,
                         cudaFuncAttributeMaxDynamicSharedMemorySize, CONV_SMEM_BYTES);

    ln_kernel<0><<<(Bc*Lc)/8, 256>>>(x, ln1_g, ln1_b);
    qkv_kernel<<<(Bc*Lc)/16, 144>>>(wq, bq, wk, bk, wv, bv);
    attn_kernel<<<dim3(Lc/256, Hc, Bc), 128>>>();
    proj_kernel<<<(Bc*Lc)/16, 192>>>(x, wo, bo);
    ln_kernel<1><<<(Bc*Lc)/8, 256>>>(x, ln2_g, ln2_b);
    conv_mma_kernel<0><<<dim3(Lc/64, Bc), 256, CONV_SMEM_BYTES>>>(c1_w, c1_b, outp);
    conv_mma_kernel<1><<<dim3(Lc/64, Bc), 256, CONV_SMEM_BYTES>>>(c2_w, c2_b, outp);
}

// round 6
// speedup vs baseline: 1.6030x; 1.1181x over previous
#include <cuda_runtime.h>
#include <math.h>
#include <stdint.h>

#define Bc 16
#define Lc 2048
#define Dc 192
#define Hc 4
#define Kc 12

// ---------------- scratch (no allocations allowed) ----------------
__device__ float g_xn [(size_t)Bc*Lc*Dc];       // xn1 then xn2 (reused)
__device__ float g_q  [(size_t)Bc*Hc*Lc*Kc];    // [B,H,L,K]
__device__ float g_k  [(size_t)Bc*Hc*Lc*Kc];
__device__ float g_v  [(size_t)Bc*Hc*Lc*Kc];
__device__ float g_ctx[(size_t)Bc*Lc*Hc*Kc];    // [B,L,H,K]
__device__ float g_y1 [(size_t)Bc*Lc*Dc];       // x + MHA
__device__ float g_h  [(size_t)Bc*Lc*Dc];       // relu(conv1), zero rows 0, L-1

__device__ __forceinline__ float ex2(float x) {
    float y; asm("ex2.approx.f32 %0, %1;" : "=f"(y) : "f"(x)); return y;
}
__device__ __forceinline__ float to_tf32(float x) {
    uint32_t u; asm("cvt.rna.tf32.f32 %0, %1;" : "=r"(u) : "f"(x));
    return __uint_as_float(u);
}
__device__ __forceinline__ void mma_tf32(float* c, const uint32_t* a,
                                         uint32_t b0, uint32_t b1)
{
    asm volatile(
        "mma.sync.aligned.m16n8k8.row.col.f32.tf32.tf32.f32 "
        "{%0,%1,%2,%3}, {%4,%5,%6,%7}, {%8,%9}, {%0,%1,%2,%3};"
        : "+f"(c[0]), "+f"(c[1]), "+f"(c[2]), "+f"(c[3])
        : "r"(a[0]), "r"(a[1]), "r"(a[2]), "r"(a[3]), "r"(b0), "r"(b1));
}

// ---------------- LayerNorm: one warp per row ----------------
template<int SRC>
__global__ void ln_kernel(const float* __restrict__ xin,
                          const float* __restrict__ gamma,
                          const float* __restrict__ beta)
{
    int gw   = (blockIdx.x * blockDim.x + threadIdx.x) >> 5;
    int lane = threadIdx.x & 31;
    if (gw >= Bc * Lc) return;
    const float* row = (SRC == 0 ? xin : g_y1) + (size_t)gw * Dc;
    float v[6];
    float s = 0.f;
#pragma unroll
    for (int i = 0; i < 6; i++) { v[i] = row[lane + 32*i]; s += v[i]; }
#pragma unroll
    for (int o = 16; o; o >>= 1) s += __shfl_xor_sync(0xffffffffu, s, o);
    float mean = s * (1.f/192.f);
    float vs = 0.f;
#pragma unroll
    for (int i = 0; i < 6; i++) { float d = v[i] - mean; vs += d*d; }
#pragma unroll
    for (int o = 16; o; o >>= 1) vs += __shfl_xor_sync(0xffffffffu, vs, o);
    float inv = rsqrtf(vs * (1.f/192.f) + 1e-3f);
#pragma unroll
    for (int i = 0; i < 6; i++) {
        int c = lane + 32*i;
        g_xn[(size_t)gw * Dc + c] = (v[i] - mean) * inv * gamma[c] + beta[c];
    }
}

// ---------------- QKV projection: tf32 MMA, M=64, N=3x48, K=192 ----------------
#define QA_S 196
#define QB_S 152
#define QA_FLOATS (64 * QA_S)
#define QB_FLOATS (32 * QB_S)
#define QKV_SMEM_BYTES ((QA_FLOATS + 2 * QB_FLOATS) * 4)

__global__ __launch_bounds__(192, 2)
void qkv_mma_kernel(const float* __restrict__ wq, const float* __restrict__ bq,
                    const float* __restrict__ wk, const float* __restrict__ bk,
                    const float* __restrict__ wv, const float* __restrict__ bv)
{
    extern __shared__ float smem[];
    float* sA = smem;                 // [64][196] tf32 xn rows
    float* sB = smem + QA_FLOATS;     // [2][32][152] tf32 weights (q|k|v cols)

    const int tid  = threadIdx.x;
    const int w    = tid >> 5;
    const int lane = tid & 31;
    const int tig  = lane & 3;
    const int grp  = lane >> 2;
    const int rowbase = blockIdx.x * 64;
    const int bb   = rowbase / Lc;
    const int lloc = rowbase % Lc;

    for (int idx = tid; idx < 64 * 48; idx += 192) {
        int r = idx / 48, c4 = (idx % 48) * 4;
        float4 v = *(const float4*)(g_xn + (size_t)(rowbase + r) * Dc + c4);
        float* d = sA + r * QA_S + c4;
        d[0] = to_tf32(v.x); d[1] = to_tf32(v.y);
        d[2] = to_tf32(v.z); d[3] = to_tf32(v.w);
    }

    auto loadW = [&](int kc, int bf) {
        float* dstb = sB + bf * QB_FLOATS;
#pragma unroll
        for (int it = 0; it < 6; it++) {
            int idx = tid + it * 192;            // 32*36 float4 = 1152
            int k = idx / 36, c = (idx % 36) * 4;
            int m = c / 48, lc = c % 48;
            const float* src = (m == 0) ? wq : (m == 1) ? wk : wv;
            float4 v = *(const float4*)(src + (size_t)(kc * 32 + k) * 48 + lc);
            float* d = dstb + k * QB_S + c;
            d[0] = to_tf32(v.x); d[1] = to_tf32(v.y);
            d[2] = to_tf32(v.z); d[3] = to_tf32(v.w);
        }
    };

    const int s     = w >> 1;
    const int mbase = (w & 1) * 32;
    float c[2][6][4];
#pragma unroll
    for (int i = 0; i < 2; i++)
#pragma unroll
        for (int j = 0; j < 6; j++)
#pragma unroll
            for (int q = 0; q < 4; q++) c[i][j][q] = 0.f;

    loadW(0, 0);
    __syncthreads();
    int buf = 0;
    for (int kc = 0; kc < 6; kc++) {
        if (kc < 5) loadW(kc + 1, buf ^ 1);
        const float* bBuf = sB + buf * QB_FLOATS + s * 48;
#pragma unroll
        for (int ks = 0; ks < 4; ks++) {
            const int c0 = kc * 32 + ks * 8;
            uint32_t a[2][4];
#pragma unroll
            for (int mt = 0; mt < 2; mt++) {
                const float* ap = sA + (mbase + mt * 16 + grp) * QA_S + c0 + tig;
                a[mt][0] = __float_as_uint(ap[0]);
                a[mt][1] = __float_as_uint(ap[8 * QA_S]);
                a[mt][2] = __float_as_uint(ap[4]);
                a[mt][3] = __float_as_uint(ap[8 * QA_S + 4]);
            }
            const float* bp = bBuf + (ks * 8 + tig) * QB_S + grp;
#pragma unroll
            for (int nt = 0; nt < 6; nt++) {
                uint32_t b0 = __float_as_uint(bp[nt * 8]);
                uint32_t b1 = __float_as_uint(bp[nt * 8 + 4 * QB_S]);
                mma_tf32(c[0][nt], a[0], b0, b1);
                mma_tf32(c[1][nt], a[1], b0, b1);
            }
        }
        __syncthreads();
        buf ^= 1;
    }

    const float* Bp = (s == 0) ? bq : (s == 1) ? bk : bv;
    float* O = (s == 0) ? g_q : (s == 1) ? g_k : g_v;
#pragma unroll
    for (int mt = 0; mt < 2; mt++) {
#pragma unroll
        for (int rs = 0; rs < 2; rs++) {
            int l = lloc + mbase + mt * 16 + grp + rs * 8;
#pragma unroll
            for (int nt = 0; nt < 6; nt++) {
                int n = nt * 8 + tig * 2;       // 0..47, even
                int h = n / 12, kk = n % 12;    // kk even -> pair stays in-row
                float2 res;
                res.x = c[mt][nt][rs * 2 + 0] + Bp[n];
                res.y = c[mt][nt][rs * 2 + 1] + Bp[n + 1];
                *(float2*)(O + (((size_t)bb * Hc + h) * Lc + l) * Kc + kk) = res;
            }
        }
    }
}

// ---------------- causal attention: 4 queries/thread ----------------
// block 128 threads -> 512 queries; queries l_i = 512*qt + t + 128*i.
// J = index of masked query: i<J skip, i==J masked (mm<=t), i>J full.
// J=-1 -> all queries full (interior tiles).
template<int J>
__device__ __forceinline__ void attn_tile4(const float4* __restrict__ sk,
                                           const float4* __restrict__ sv,
                                           int t, const float q[4][12],
                                           float o[4][12], float* d)
{
#pragma unroll 2
    for (int mm = 0; mm < 128; mm++) {
        float4 ka = sk[3*mm], kb = sk[3*mm+1], kc = sk[3*mm+2];
        float p[4];
#pragma unroll
        for (int i = 0; i < 4; i++) {
            if (i < J) continue;
            float s = q[i][0]*ka.x + q[i][1]*ka.y + q[i][2]*ka.z + q[i][3]*ka.w
                    + q[i][4]*kb.x + q[i][5]*kb.y + q[i][6]*kb.z + q[i][7]*kb.w
                    + q[i][8]*kc.x + q[i][9]*kc.y + q[i][10]*kc.z + q[i][11]*kc.w;
            p[i] = ex2(s);
            if (i == J && mm > t) p[i] = 0.f;
            d[i] += p[i];
        }
        float4 va = sv[3*mm], vb = sv[3*mm+1], vc = sv[3*mm+2];
#pragma unroll
        for (int i = 0; i < 4; i++) {
            if (i < J) continue;
            o[i][0] += p[i]*va.x; o[i][1] += p[i]*va.y; o[i][2]  += p[i]*va.z; o[i][3]  += p[i]*va.w;
            o[i][4] += p[i]*vb.x; o[i][5] += p[i]*vb.y; o[i][6]  += p[i]*vb.z; o[i][7]  += p[i]*vb.w;
            o[i][8] += p[i]*vc.x; o[i][9] += p[i]*vc.y; o[i][10] += p[i]*vc.z; o[i][11] += p[i]*vc.w;
        }
    }
}

__global__ void attn_kernel()
{
    __shared__ float4 sk[128 * 3];
    __shared__ float4 sv[128 * 3];
    int qt = gridDim.x - 1 - blockIdx.x;    // heavy tiles first
    int h = blockIdx.y, bb = blockIdx.z;
    int t = threadIdx.x;

    size_t head = ((size_t)bb * Hc + h) * Lc * Kc;
    const float4* qb = (const float4*)(g_q + head);
    const float*  kb = g_k + head;
    const float*  vb = g_v + head;

    const float scale = 0.4164682333693345f;   // log2(e)/sqrt(12)
    float q[4][12], o[4][12], d[4];
#pragma unroll
    for (int i = 0; i < 4; i++) {
        int l = qt * 512 + t + 128 * i;
        float4 a = qb[3*l], b = qb[3*l+1], c = qb[3*l+2];
        q[i][0]=a.x*scale; q[i][1]=a.y*scale; q[i][2]=a.z*scale; q[i][3]=a.w*scale;
        q[i][4]=b.x*scale; q[i][5]=b.y*scale; q[i][6]=b.z*scale; q[i][7]=b.w*scale;
        q[i][8]=c.x*scale; q[i][9]=c.y*scale; q[i][10]=c.z*scale; q[i][11]=c.w*scale;
        d[i] = 0.f;
#pragma unroll
        for (int j = 0; j < 12; j++) o[i][j] = 0.f;
    }

    int full = 4 * qt;
    for (int kt = 0; kt < full + 4; kt++) {
        __syncthreads();
        const float4* ks = (const float4*)(kb + (size_t)kt * 128 * Kc);
        const float4* vs = (const float4*)(vb + (size_t)kt * 128 * Kc);
        for (int i = t; i < 128 * 3; i += 128) { sk[i] = ks[i]; sv[i] = vs[i]; }
        __syncthreads();
        if      (kt <  full)     attn_tile4<-1>(sk, sv, t, q, o, d);  // all full
        else if (kt == full)     attn_tile4<0>(sk, sv, t, q, o, d);
        else if (kt == full + 1) attn_tile4<1>(sk, sv, t, q, o, d);
        else if (kt == full + 2) attn_tile4<2>(sk, sv, t, q, o, d);
        else                     attn_tile4<3>(sk, sv, t, q, o, d);
    }

#pragma unroll
    for (int i = 0; i < 4; i++) {
        float inv = 1.f / d[i];
        int l = qt * 512 + t + 128 * i;
        float4* out = (float4*)(g_ctx + (((size_t)bb * Lc + l) * Hc + h) * Kc);
        out[0] = make_float4(o[i][0]*inv, o[i][1]*inv, o[i][2]*inv,  o[i][3]*inv);
        out[1] = make_float4(o[i][4]*inv, o[i][5]*inv, o[i][6]*inv,  o[i][7]*inv);
        out[2] = make_float4(o[i][8]*inv, o[i][9]*inv, o[i][10]*inv, o[i][11]*inv);
    }
}

// ---------------- output projection + residual: tf32 MMA ----------------
#define PA_S 52
#define PB_S 200
#define PA_FLOATS (64 * PA_S)
#define PB_FLOATS (48 * PB_S)
#define PROJ_SMEM_BYTES ((PA_FLOATS + PB_FLOATS) * 4)

__global__ __launch_bounds__(256, 4)
void proj_mma_kernel(const float* __restrict__ x,
                     const float* __restrict__ wo,
                     const float* __restrict__ bo)
{
    extern __shared__ float smem[];
    float* sA = smem;                 // [64][52]  ctx rows, tf32
    float* sB = smem + PA_FLOATS;     // [48][200] wo, tf32

    const int tid  = threadIdx.x;
    const int w    = tid >> 5;
    const int lane = tid & 31;
    const int tig  = lane & 3;
    const int grp  = lane >> 2;
    const int rowbase = blockIdx.x * 64;

    for (int idx = tid; idx < 64 * 12; idx += 256) {
        int r = idx / 12, c4 = (idx % 12) * 4;
        float4 v = *(const float4*)(g_ctx + (size_t)(rowbase + r) * 48 + c4);
        float* d = sA + r * PA_S + c4;
        d[0] = to_tf32(v.x); d[1] = to_tf32(v.y);
        d[2] = to_tf32(v.z); d[3] = to_tf32(v.w);
    }
    for (int idx = tid; idx < 48 * 48; idx += 256) {
        int r = idx / 48, c4 = (idx % 48) * 4;
        float4 v = *(const float4*)(wo + (size_t)r * Dc + c4);
        float* d = sB + r * PB_S + c4;
        d[0] = to_tf32(v.x); d[1] = to_tf32(v.y);
        d[2] = to_tf32(v.z); d[3] = to_tf32(v.w);
    }
    __syncthreads();

    const int mbase = (w & 1) * 32;
    const int nbase = (w >> 1) * 48;
    float c[2][6][4];
#pragma unroll
    for (int i = 0; i < 2; i++)
#pragma unroll
        for (int j = 0; j < 6; j++)
#pragma unroll
            for (int q = 0; q < 4; q++) c[i][j][q] = 0.f;

#pragma unroll
    for (int ks = 0; ks < 6; ks++) {
        const int c0 = ks * 8;
        uint32_t a[2][4];
#pragma unroll
        for (int mt = 0; mt < 2; mt++) {
            const float* ap = sA + (mbase + mt * 16 + grp) * PA_S + c0 + tig;
            a[mt][0] = __float_as_uint(ap[0]);
            a[mt][1] = __float_as_uint(ap[8 * PA_S]);
            a[mt][2] = __float_as_uint(ap[4]);
            a[mt][3] = __float_as_uint(ap[8 * PA_S + 4]);
        }
        const float* bp = sB + (c0 + tig) * PB_S + nbase + grp;
#pragma unroll
        for (int nt = 0; nt < 6; nt++) {
            uint32_t b0 = __float_as_uint(bp[nt * 8]);
            uint32_t b1 = __float_as_uint(bp[nt * 8 + 4 * PB_S]);
            mma_tf32(c[0][nt], a[0], b0, b1);
            mma_tf32(c[1][nt], a[1], b0, b1);
        }
    }

#pragma unroll
    for (int mt = 0; mt < 2; mt++) {
#pragma unroll
        for (int rs = 0; rs < 2; rs++) {
            size_t row = rowbase + mbase + mt * 16 + grp + rs * 8;
#pragma unroll
            for (int nt = 0; nt < 6; nt++) {
                int n = nbase + nt * 8 + tig * 2;
                size_t off = row * Dc + n;
                float2 xv = *(const float2*)(x + off);
                float2 res;
                res.x = c[mt][nt][rs * 2 + 0] + bo[n]     + xv.x;
                res.y = c[mt][nt][rs * 2 + 1] + bo[n + 1] + xv.y;
                *(float2*)(g_y1 + off) = res;
            }
        }
    }
}

// ---------------- conv1d as tf32 tensor-core GEMM ----------------
#define SA_STRIDE 196
#define SB_STRIDE 200
#define SA_FLOATS (66 * SA_STRIDE)
#define SB_FLOATS (32 * SB_STRIDE)
#define CONV_SMEM_BYTES ((SA_FLOATS + 2 * SB_FLOATS) * 4)

template<int MODE>
__global__ __launch_bounds__(256, 2)
void conv_mma_kernel(const float* __restrict__ W,
                     const float* __restrict__ bias,
                     float* __restrict__ out)
{
    extern __shared__ float smem[];
    float* sA = smem;                    // [66][196]
    float* sB = smem + SA_FLOATS;        // [2][32][200]

    const int tid  = threadIdx.x;
    const int w    = tid >> 5;
    const int lane = tid & 31;
    const int tig  = lane & 3;
    const int grp  = lane >> 2;
    const int l0   = blockIdx.x * 64;
    const int bb   = blockIdx.y;
    const float* srcb = ((MODE == 0) ? g_xn : g_h) + (size_t)bb * Lc * Dc;

    for (int idx = tid; idx < 66 * 48; idx += 256) {
        int r = idx / 48, c4 = (idx % 48) * 4;
        int l = l0 - 1 + r; l = l < 0 ? 0 : (l > Lc - 1 ? Lc - 1 : l);
        float4 v = *(const float4*)(srcb + (size_t)l * Dc + c4);
        float* d = sA + r * SA_STRIDE + c4;
        d[0] = to_tf32(v.x); d[1] = to_tf32(v.y);
        d[2] = to_tf32(v.z); d[3] = to_tf32(v.w);
    }

    const int mbase = (w & 1) * 32;
    const int nbase = (w >> 1) * 48;
    float c[2][6][4];
#pragma unroll
    for (int i = 0; i < 2; i++)
#pragma unroll
        for (int j = 0; j < 6; j++)
#pragma unroll
            for (int q = 0; q < 4; q++) c[i][j][q] = 0.f;

    auto loadW = [&](int kc, int bf) {
        float* dstb = sB + bf * SB_FLOATS;
#pragma unroll
        for (int it = 0; it < 6; it++) {
            int idx = tid + it * 256;
            int k = idx / 48, c4 = (idx % 48) * 4;
            float4 v = *(const float4*)(W + ((size_t)(kc * 32 + k)) * Dc + c4);
            float* d = dstb + k * SB_STRIDE + c4;
            d[0] = to_tf32(v.x); d[1] = to_tf32(v.y);
            d[2] = to_tf32(v.z); d[3] = to_tf32(v.w);
        }
    };

    loadW(0, 0);
    __syncthreads();

    int buf = 0;
    for (int kc = 0; kc < 18; kc++) {
        if (kc < 17) loadW(kc + 1, buf ^ 1);
        const int t  = kc / 6;
        const int cc = (kc % 6) * 32;
        const float* bBuf = sB + buf * SB_FLOATS;
#pragma unroll
        for (int ks = 0; ks < 4; ks++) {
            const int c0 = cc + ks * 8;
            uint32_t a[2][4];
#pragma unroll
            for (int mt = 0; mt < 2; mt++) {
                const float* ap = sA + (mbase + mt * 16 + grp + t) * SA_STRIDE + c0 + tig;
                a[mt][0] = __float_as_uint(ap[0]);
                a[mt][1] = __float_as_uint(ap[8 * SA_STRIDE]);
                a[mt][2] = __float_as_uint(ap[4]);
                a[mt][3] = __float_as_uint(ap[8 * SA_STRIDE + 4]);
            }
            const float* bp = bBuf + (ks * 8 + tig) * SB_STRIDE + nbase + grp;
#pragma unroll
            for (int nt = 0; nt < 6; nt++) {
                uint32_t b0 = __float_as_uint(bp[nt * 8]);
                uint32_t b1 = __float_as_uint(bp[nt * 8 + 4 * SB_STRIDE]);
                mma_tf32(c[0][nt], a[0], b0, b1);
                mma_tf32(c[1][nt], a[1], b0, b1);
            }
        }
        __syncthreads();
        buf ^= 1;
    }

    float* dst = (MODE == 0) ? g_h : out;
#pragma unroll
    for (int mt = 0; mt < 2; mt++) {
#pragma unroll
        for (int rs = 0; rs < 2; rs++) {
            int l = l0 + mbase + mt * 16 + grp + rs * 8;
            bool interior = (l >= 1) && (l <= Lc - 2);
            size_t rowoff = ((size_t)bb * Lc + l) * Dc;
#pragma unroll
            for (int nt = 0; nt < 6; nt++) {
                int n = nbase + nt * 8 + tig * 2;
                float v0 = c[mt][nt][rs * 2 + 0] + bias[n];
                float v1 = c[mt][nt][rs * 2 + 1] + bias[n + 1];
                float2 res;
                if (MODE == 0) {
                    res.x = interior ? fmaxf(v0, 0.f) : 0.f;
                    res.y = interior ? fmaxf(v1, 0.f) : 0.f;
                } else {
                    float2 y = *(const float2*)(g_y1 + rowoff + n);
                    res.x = y.x + (interior ? v0 : 0.f);
                    res.y = y.y + (interior ? v1 : 0.f);
                }
                *(float2*)(dst + rowoff + n) = res;
            }
        }
    }
}

// ---------------- launcher ----------------
extern "C" void kernel_launch(void* const* d_in, const int* in_sizes, int n_in,
                              void* d_out, int out_size)
{
    const float* x     = (const float*)d_in[0];
    const float* ln1_g = (const float*)d_in[1];
    const float* ln1_b = (const float*)d_in[2];
    const float* wq    = (const float*)d_in[3];
    const float* bq    = (const float*)d_in[4];
    const float* wk    = (const float*)d_in[5];
    const float* bk    = (const float*)d_in[6];
    const float* wv    = (const float*)d_in[7];
    const float* bv    = (const float*)d_in[8];
    const float* wo    = (const float*)d_in[9];
    const float* bo    = (const float*)d_in[10];
    const float* ln2_g = (const float*)d_in[11];
    const float* ln2_b = (const float*)d_in[12];
    const float* c1_w  = (const float*)d_in[13];
    const float* c1_b  = (const float*)d_in[14];
    const float* c2_w  = (const float*)d_in[15];
    const float* c2_b  = (const float*)d_in[16];
    float* outp = (float*)d_out;

    cudaFuncSetAttribute(conv_mma_kernel<0>,
                         cudaFuncAttributeMaxDynamicSharedMemorySize, CONV_SMEM_BYTES);
    cudaFuncSetAttribute(conv_mma_kernel<1>,
                         cudaFuncAttributeMaxDynamicSharedMemorySize, CONV_SMEM_BYTES);
    cudaFuncSetAttribute(qkv_mma_kernel,
                         cudaFuncAttributeMaxDynamicSharedMemorySize, QKV_SMEM_BYTES);
    cudaFuncSetAttribute(proj_mma_kernel,
                         cudaFuncAttributeMaxDynamicSharedMemorySize, PROJ_SMEM_BYTES);

    ln_kernel<0><<<(Bc*Lc)/8, 256>>>(x, ln1_g, ln1_b);
    qkv_mma_kernel<<<(Bc*Lc)/64, 192, QKV_SMEM_BYTES>>>(wq, bq, wk, bk, wv, bv);
    attn_kernel<<<dim3(Lc/512, Hc, Bc), 128>>>();
    proj_mma_kernel<<<(Bc*Lc)/64, 256, PROJ_SMEM_BYTES>>>(x, wo, bo);
    ln_kernel<1><<<(Bc*Lc)/8, 256>>>(x, ln2_g, ln2_b);
    conv_mma_kernel<0><<<dim3(Lc/64, Bc), 256, CONV_SMEM_BYTES>>>(c1_w, c1_b, outp);
    conv_mma_kernel<1><<<dim3(Lc/64, Bc), 256, CONV_SMEM_BYTES>>>(c2_w, c2_b, outp);
}